// round 13
// baseline (speedup 1.0000x reference)
#include <cuda_runtime.h>
#include <cuda_fp16.h>
#include <cstdint>

#define N_EDGES_C 500000
#define N1 448
#define N2 256
#define N3 128
#define KY 416
#define KW1 832
#define SA_Y 424
#define SA2 456
#define SA3 264
#define SO3 136
#define SBS32 40
#define BS32BYTES 35840   // prep_y B buf (448 rows)
#define BSE 20480         // edge B buf (<=256 rows x 40 h x 2B)

__device__ __half g_zc[(size_t)20000 * KY];
__device__ __half g_w1[(size_t)N1 * KW1];
__device__ __half g_w2[(size_t)N2 * N1];
__device__ __half g_w3[(size_t)N3 * N2];
__device__ __half g_ytop[(size_t)20000 * N1];
__device__ __half g_ybot[(size_t)20000 * N1];
__device__ int g_idx64;

__device__ __forceinline__ uint32_t smem_u32(const void* p) {
    uint32_t a;
    asm("{ .reg .u64 t; cvta.to.shared.u64 t, %1; cvt.u32.u64 %0, t; }" : "=r"(a) : "l"(p));
    return a;
}
#define LDSM4(r0, r1, r2, r3, a) \
    asm volatile("ldmatrix.sync.aligned.m8n8.x4.shared.b16 {%0,%1,%2,%3}, [%4];" \
                 : "=r"(r0), "=r"(r1), "=r"(r2), "=r"(r3) : "r"(a))
#define LDSM2(r0, r1, a) \
    asm volatile("ldmatrix.sync.aligned.m8n8.x2.shared.b16 {%0,%1}, [%2];" \
                 : "=r"(r0), "=r"(r1) : "r"(a))
#define HMMA(d, a0, a1, a2, a3, b0, b1) \
    asm volatile("mma.sync.aligned.m16n8k16.row.col.f32.f16.f16.f32 " \
                 "{%0,%1,%2,%3}, {%4,%5,%6,%7}, {%8,%9}, {%0,%1,%2,%3};" \
                 : "+f"((d)[0]), "+f"((d)[1]), "+f"((d)[2]), "+f"((d)[3]) \
                 : "r"(a0), "r"(a1), "r"(a2), "r"(a3), "r"(b0), "r"(b1))
#define CPA16(dst, src) \
    asm volatile("cp.async.ca.shared.global [%0], [%1], 16;" :: "r"(dst), "l"(src))
#define CPA_COMMIT() asm volatile("cp.async.commit_group;" ::: "memory")
#define CPA_WAIT(n)  asm volatile("cp.async.wait_group %0;" :: "n"(n) : "memory")

__global__ void detect_idx(const int* ei) {
    int z = 0;
    for (int i = 0; i < 64; i++) z |= ei[2 * i + 1];
    g_idx64 = (z == 0) ? 1 : 0;
}

// ---------- P1: node MLP + zc (4 nodes/block) ----------
__global__ void __launch_bounds__(256) prep_nodes(
    const float* __restrict__ z, const float* __restrict__ cell,
    const float* __restrict__ esm,
    const float* __restrict__ w1, const float* __restrict__ b1,
    const float* __restrict__ w2, const float* __restrict__ b2,
    const float* __restrict__ w3, const float* __restrict__ b3) {
    __shared__ float sc[4][4], h1[4][64], h2[4][32], m16[4][16];
    const int sub = threadIdx.x >> 6, t = threadIdx.x & 63;
    const int i = blockIdx.x * 4 + sub;
    if (t < 4) sc[sub][t] = cell[i * 4 + t];
    __syncthreads();
    {
        float s = b1[t];
        for (int j = 0; j < 4; j++) s += sc[sub][j] * w1[j * 64 + t];
        h1[sub][t] = fmaxf(s, 0.f);
    }
    __syncthreads();
    if (t < 32) {
        float s = b2[t];
        for (int j = 0; j < 64; j++) s += h1[sub][j] * w2[j * 32 + t];
        h2[sub][t] = fmaxf(s, 0.f);
    }
    __syncthreads();
    if (t < 16) {
        float s = b3[t];
        for (int j = 0; j < 32; j++) s += h2[sub][j] * w3[j * 16 + t];
        m16[sub][t] = s;
    }
    __syncthreads();
    for (int col = t; col < KY; col += 64) {
        float v = 0.f;
        if (col < 64)       v = z[i * 64 + col];
        else if (col < 80)  v = m16[sub][col - 64];
        else if (col < 400) v = esm[i * 320 + (col - 80)];
        g_zc[(size_t)i * KY + col] = __float2half_rn(v);
    }
}

// ---------- P2: weights K-major f16, padded ----------
__global__ void prep_weights(const float* __restrict__ fw1, const float* __restrict__ fw2,
                             const float* __restrict__ fw3) {
    int i = blockIdx.x * blockDim.x + threadIdx.x;
    const int T1 = N1 * KW1, T2 = N2 * N1, T3 = N3 * N2;
    if (i < T1) {
        int n = i / KW1, k = i % KW1;
        float v = 0.f;
        if (n < 400) {
            if (k < 416) { if (k < 400) v = fw1[k * 400 + n]; }
            else { int kk = k - 416; if (kk < 400) v = fw1[(400 + kk) * 400 + n]; }
        }
        g_w1[i] = __float2half_rn(v);
    } else if (i < T1 + T2) {
        int j = i - T1, n = j / N1, k = j % N1;
        g_w2[j] = __float2half_rn((n < 200 && k < 400) ? fw2[k * 200 + n] : 0.f);
    } else if (i < T1 + T2 + T3) {
        int j = i - T1 - T2, n = j / N2, k = j % N2;
        g_w3[j] = __float2half_rn((n < 100 && k < 200) ? fw3[k * 100 + n] : 0.f);
    }
}

// ---------- gemm32 (512 thr, 2Mx8N) for prep_y ----------
template <int NTILES, int NCH, int ROWS, int KW, int PAR, bool SKIP0, int ROWS2, int KW2>
__device__ __forceinline__ void gemm32(const __half* __restrict__ W, const __half* __restrict__ Wnext,
                                       uint32_t aA, uint32_t aB, int SA,
                                       float* acc, int wm, int wn, int lane, int tid) {
#pragma unroll
    for (int i = 0; i < 2 * NTILES * 4; i++) acc[i] = 0.f;
    constexpr int NLD = (ROWS * 4 + 511) / 512;
    if (!SKIP0) {
#pragma unroll
        for (int j = 0; j < NLD; j++) {
            int i = tid + j * 512;
            if (i < ROWS * 4) CPA16(aB + PAR * BS32BYTES + (((i >> 2) * SBS32 + (i & 3) * 8) << 1),
                                    W + (size_t)(i >> 2) * KW + (i & 3) * 8);
        }
        CPA_COMMIT();
    }
    const uint32_t brow = wn * (NTILES * 8) + (lane & 7) + ((lane >> 4) << 3);
#pragma unroll 1
    for (int c = 0; c < NCH; c++) {
        const int cur = (c + PAR) & 1;
        if (c + 1 < NCH) {
            const uint32_t bofs = (cur ^ 1) * BS32BYTES;
#pragma unroll
            for (int j = 0; j < NLD; j++) {
                int i = tid + j * 512;
                if (i < ROWS * 4) CPA16(aB + bofs + (((i >> 2) * SBS32 + (i & 3) * 8) << 1),
                                        W + (size_t)(i >> 2) * KW + (c + 1) * 32 + (i & 3) * 8);
            }
            CPA_COMMIT();
            CPA_WAIT(1);
        } else if (ROWS2 > 0) {
            constexpr int NLD2 = (ROWS2 * 4 + 511) / 512;
            const uint32_t bofs = (cur ^ 1) * BS32BYTES;
#pragma unroll
            for (int j = 0; j < NLD2; j++) {
                int i = tid + j * 512;
                if (i < ROWS2 * 4) CPA16(aB + bofs + (((i >> 2) * SBS32 + (i & 3) * 8) << 1),
                                         Wnext + (size_t)(i >> 2) * KW2 + (i & 3) * 8);
            }
            CPA_COMMIT();
            CPA_WAIT(1);
        } else CPA_WAIT(0);
        __syncthreads();
        const uint32_t bbase = aB + cur * BS32BYTES;
#pragma unroll
        for (int s = 0; s < 2; s++) {
            uint32_t aaddr = aA + (((wm * 32 + (lane & 15)) * SA + c * 32 + s * 16 + ((lane >> 4) << 3)) << 1);
            uint32_t a0, a1, a2, a3, e0, e1, e2, e3;
            LDSM4(a0, a1, a2, a3, aaddr);
            LDSM4(e0, e1, e2, e3, aaddr + 16 * SA * 2);
            uint32_t baddr = bbase + ((brow * SBS32 + s * 16 + (((lane >> 3) & 1) << 3)) << 1);
#pragma unroll
            for (int g = 0; g < NTILES / 2; g++) {
                uint32_t b0, b1, b2, b3;
                LDSM4(b0, b1, b2, b3, baddr + g * (16 * SBS32 * 2));
                HMMA(acc + (2 * g) * 4, a0, a1, a2, a3, b0, b1);
                HMMA(acc + (2 * g + 1) * 4, a0, a1, a2, a3, b2, b3);
                HMMA(acc + (NTILES + 2 * g) * 4, e0, e1, e2, e3, b0, b1);
                HMMA(acc + (NTILES + 2 * g + 1) * 4, e0, e1, e2, e3, b2, b3);
            }
            if (NTILES & 1) {
                uint32_t b0, b1;
                LDSM2(b0, b1, baddr + (NTILES / 2) * (16 * SBS32 * 2));
                HMMA(acc + (NTILES - 1) * 4, a0, a1, a2, a3, b0, b1);
                HMMA(acc + (2 * NTILES - 1) * 4, e0, e1, e2, e3, b0, b1);
            }
        }
        __syncthreads();
    }
}

// ---------- prep_y (f16 output) ----------
#define SMY_A 0
#define SMY_B 54272
#define SMEM_Y (SMY_B + 2 * BS32BYTES)   // 125952

__global__ void __launch_bounds__(512) prep_y_kernel() {
    extern __shared__ char smem[];
    const uint32_t aA = smem_u32(smem + SMY_A);
    const uint32_t aB = smem_u32(smem + SMY_B);
    const int tid = threadIdx.x;
    const int wid = tid >> 5, lane = tid & 31;
    const int wm = wid & 1, wn = wid >> 1;
    const int base = blockIdx.x * 64;

    for (int i = tid; i < N1 * 4; i += 512)
        CPA16(aB + (((i >> 2) * SBS32 + (i & 3) * 8) << 1), g_w1 + (size_t)(i >> 2) * KW1 + (i & 3) * 8);
    CPA_COMMIT();
    for (int i = tid; i < 64 * 52; i += 512) {
        int r = i / 52, u = i % 52;
        int grow = base + r; if (grow > 19999) grow = 19999;
        CPA16(aA + ((r * SA_Y + u * 8) << 1), g_zc + (size_t)grow * KY + u * 8);
    }
    CPA_COMMIT();

    float acc[56];
    gemm32<7, 13, N1, KW1, 0, true, N1, KW1>(g_w1, g_w1 + 416, aA, aB, SA_Y, acc, wm, wn, lane, tid);
#pragma unroll
    for (int mt = 0; mt < 2; mt++) {
        int r0 = base + wm * 32 + mt * 16 + (lane >> 2);
#pragma unroll
        for (int nt = 0; nt < 7; nt++) {
            int c = wn * 56 + nt * 8 + (lane & 3) * 2;
            float* d = acc + (mt * 7 + nt) * 4;
            if (r0 < 20000) *(__half2*)(g_ytop + (size_t)r0 * N1 + c) = __floats2half2_rn(d[0], d[1]);
            if (r0 + 8 < 20000) *(__half2*)(g_ytop + (size_t)(r0 + 8) * N1 + c) = __floats2half2_rn(d[2], d[3]);
        }
    }
    gemm32<7, 13, N1, KW1, 1, true, 0, 0>(g_w1 + 416, nullptr, aA, aB, SA_Y, acc, wm, wn, lane, tid);
#pragma unroll
    for (int mt = 0; mt < 2; mt++) {
        int r0 = base + wm * 32 + mt * 16 + (lane >> 2);
#pragma unroll
        for (int nt = 0; nt < 7; nt++) {
            int c = wn * 56 + nt * 8 + (lane & 3) * 2;
            float* d = acc + (mt * 7 + nt) * 4;
            if (r0 < 20000) *(__half2*)(g_ybot + (size_t)r0 * N1 + c) = __floats2half2_rn(d[0], d[1]);
            if (r0 + 8 < 20000) *(__half2*)(g_ybot + (size_t)(r0 + 8) * N1 + c) = __floats2half2_rn(d[2], d[3]);
        }
    }
}

// ---------- gemm32e (256 thr, 2Mx4N, M=64) for edge kernel ----------
template <int NTILES, int NCH, int ROWS, int KW>
__device__ __forceinline__ void gemm32e(const __half* __restrict__ W,
                                        uint32_t aA, uint32_t aB, int SA,
                                        float* acc, int wm, int wn, int lane, int tid) {
#pragma unroll
    for (int i = 0; i < 2 * NTILES * 4; i++) acc[i] = 0.f;
    constexpr int NLD = ROWS * 4 / 256;
#pragma unroll
    for (int j = 0; j < NLD; j++) {
        int i = tid + j * 256;
        CPA16(aB + (((i >> 2) * SBS32 + (i & 3) * 8) << 1), W + (size_t)(i >> 2) * KW + (i & 3) * 8);
    }
    CPA_COMMIT();
    const uint32_t brow = wn * (NTILES * 8) + (lane & 7) + ((lane >> 4) << 3);
#pragma unroll 1
    for (int c = 0; c < NCH; c++) {
        const int cur = c & 1;
        if (c + 1 < NCH) {
            const uint32_t bofs = (cur ^ 1) * BSE;
#pragma unroll
            for (int j = 0; j < NLD; j++) {
                int i = tid + j * 256;
                CPA16(aB + bofs + (((i >> 2) * SBS32 + (i & 3) * 8) << 1),
                      W + (size_t)(i >> 2) * KW + (c + 1) * 32 + (i & 3) * 8);
            }
            CPA_COMMIT();
            CPA_WAIT(1);
        } else CPA_WAIT(0);
        __syncthreads();
        const uint32_t bbase = aB + cur * BSE;
#pragma unroll
        for (int s = 0; s < 2; s++) {
            uint32_t aaddr = aA + (((wm * 32 + (lane & 15)) * SA + c * 32 + s * 16 + ((lane >> 4) << 3)) << 1);
            uint32_t a0, a1, a2, a3, e0, e1, e2, e3;
            LDSM4(a0, a1, a2, a3, aaddr);
            LDSM4(e0, e1, e2, e3, aaddr + 16 * SA * 2);
            uint32_t baddr = bbase + ((brow * SBS32 + s * 16 + (((lane >> 3) & 1) << 3)) << 1);
#pragma unroll
            for (int g = 0; g < NTILES / 2; g++) {
                uint32_t b0, b1, b2, b3;
                LDSM4(b0, b1, b2, b3, baddr + g * (16 * SBS32 * 2));
                HMMA(acc + (2 * g) * 4, a0, a1, a2, a3, b0, b1);
                HMMA(acc + (2 * g + 1) * 4, a0, a1, a2, a3, b2, b3);
                HMMA(acc + (NTILES + 2 * g) * 4, e0, e1, e2, e3, b0, b1);
                HMMA(acc + (NTILES + 2 * g + 1) * 4, e0, e1, e2, e3, b2, b3);
            }
        }
        __syncthreads();
    }
}

template <int NTILES>
__device__ __forceinline__ void epi(float* acc, __half* A, int SO, const float* bias,
                                    int wm, int wn, int lane) {
#pragma unroll
    for (int mt = 0; mt < 2; mt++) {
        int r0 = wm * 32 + mt * 16 + (lane >> 2);
#pragma unroll
        for (int nt = 0; nt < NTILES; nt++) {
            int c = wn * (NTILES * 8) + nt * 8 + (lane & 3) * 2;
            float* d = acc + (mt * NTILES + nt) * 4;
            *(__half2*)(A + r0 * SO + c) =
                __floats2half2_rn(fmaxf(d[0] + bias[c], 0.f), fmaxf(d[1] + bias[c + 1], 0.f));
            *(__half2*)(A + (r0 + 8) * SO + c) =
                __floats2half2_rn(fmaxf(d[2] + bias[c], 0.f), fmaxf(d[3] + bias[c + 1], 0.f));
        }
    }
}

// ---------- edge kernel: M=64, 256 thr, 2 CTAs/SM ----------
#define SME_NS   0
#define SME_ND   256
#define SME_BIAS 512                      // 961 f32 -> ends 4356
#define SME_A    4608                     // 64 x 456 h = 58368 -> ends 62976
#define SME_B    62976                    // 2 x 20480
#define SMEM_E   (SME_B + 2 * BSE)        // 103936

__global__ void __launch_bounds__(256, 2) edge_mlp_kernel(
    const void* __restrict__ eidx_raw, const float* __restrict__ fb1,
    const float* __restrict__ fb2, const float* __restrict__ fb3,
    const float* __restrict__ fw4, const float* __restrict__ fb4,
    float* __restrict__ out) {
    extern __shared__ char smem[];
    int* ns = (int*)(smem + SME_NS);
    int* nd = (int*)(smem + SME_ND);
    float* bias = (float*)(smem + SME_BIAS);
    __half* A = (__half*)(smem + SME_A);
    const uint32_t aA = smem_u32(A);
    const uint32_t aB = smem_u32(smem + SME_B);

    const int tid = threadIdx.x;
    const int wid = tid >> 5, lane = tid & 31;
    const int wm = wid & 1, wn = wid >> 1;
    const long long base = (long long)blockIdx.x * 64;

    for (int i = tid; i < 448; i += 256) bias[i] = (i < 400) ? fb1[i] : 0.f;
    for (int i = tid; i < 256; i += 256) bias[448 + i] = (i < 200) ? fb2[i] : 0.f;
    if (tid < 128) bias[704 + tid] = (tid < 100) ? fb3[tid] : 0.f;
    else { int i = tid - 128; bias[832 + i] = (i < 100) ? fw4[i] : 0.f; }
    if (tid == 0) bias[960] = fb4[0];

    if (tid < 64) {
        long long e = base + tid;
        if (e >= N_EDGES_C) e = N_EDGES_C - 1;
        if (g_idx64) {
            const long long* ei = (const long long*)eidx_raw;
            ns[tid] = (int)ei[e]; nd[tid] = (int)ei[N_EDGES_C + e];
        } else {
            const int* ei = (const int*)eidx_raw;
            ns[tid] = ei[e]; nd[tid] = ei[N_EDGES_C + e];
        }
    }
    __syncthreads();

    // combine: act1[64][448] = f16(relu(f32(yt) + f32(yb) + b1))
    for (int i = tid; i < 64 * 56; i += 256) {
        int r = i / 56, u = i % 56;
        uint4 tv = *(const uint4*)(g_ytop + (size_t)ns[r] * N1 + u * 8);
        uint4 bv = *(const uint4*)(g_ybot + (size_t)nd[r] * N1 + u * 8);
        const __half2* tp = (const __half2*)&tv;
        const __half2* bp = (const __half2*)&bv;
        const float* bb = bias + u * 8;
        __half2 h[4];
#pragma unroll
        for (int j = 0; j < 4; j++) {
            float2 t2 = __half22float2(tp[j]);
            float2 b2 = __half22float2(bp[j]);
            h[j] = __floats2half2_rn(fmaxf(t2.x + b2.x + bb[2 * j], 0.f),
                                     fmaxf(t2.y + b2.y + bb[2 * j + 1], 0.f));
        }
        *(uint4*)(A + r * SA2 + u * 8) = *(uint4*)h;
    }
    __syncthreads();

    float acc[64];
    // FC2: [64,448] @ W2 -> 256 (NTILES=8, k32 x14)
    gemm32e<8, 14, N2, N1>(g_w2, aA, aB, SA2, acc, wm, wn, lane, tid);
    epi<8>(acc, A, SA3, bias + 448, wm, wn, lane);
    __syncthreads();
    // FC3: [64,256] @ W3 -> 128 (NTILES=4, k32 x8)
    gemm32e<4, 8, N3, N2>(g_w3, aA, aB, SA3, acc, wm, wn, lane, tid);
    epi<4>(acc, A, SO3, bias + 704, wm, wn, lane);
    __syncthreads();

    // head: warp-cooperative dot, 8 edges/warp
#pragma unroll 1
    for (int q = 0; q < 8; q++) {
        int r = wid * 8 + q;
        const __half* ar = A + r * SO3;
        float s = 0.f;
#pragma unroll
        for (int j = 0; j < 4; j++) {
            int c = lane + j * 32;
            if (c < 100) s += __half2float(ar[c]) * bias[832 + c];
        }
#pragma unroll
        for (int o = 16; o; o >>= 1) s += __shfl_xor_sync(~0u, s, o);
        if (lane == 0) {
            long long e = base + r;
            if (e < N_EDGES_C) out[e] = s + bias[960];
        }
    }
}

extern "C" void kernel_launch(void* const* d_in, const int* in_sizes, int n_in,
                              void* d_out, int out_size) {
    static const int EXP[18] = {1280000, 1000000, 80000, 6400000, 256, 64, 2048, 32, 512, 16,
                                320000, 400, 80000, 200, 20000, 100, 100, 1};
    const void* p[18];
    bool used[32] = {false};
    for (int j = 0; j < 18; j++) {
        p[j] = (j < n_in) ? d_in[j] : nullptr;
        for (int i = 0; i < n_in && i < 32; i++) {
            if (!used[i] && in_sizes[i] == EXP[j]) { p[j] = d_in[i]; used[i] = true; break; }
        }
    }
    const float* z    = (const float*)p[0];
    const void*  ei   = p[1];
    const float* cell = (const float*)p[2];
    const float* esm  = (const float*)p[3];
    const float* mw1 = (const float*)p[4];
    const float* mb1 = (const float*)p[5];
    const float* mw2 = (const float*)p[6];
    const float* mb2 = (const float*)p[7];
    const float* mw3 = (const float*)p[8];
    const float* mb3 = (const float*)p[9];
    const float* f1w = (const float*)p[10];
    const float* f1b = (const float*)p[11];
    const float* f2w = (const float*)p[12];
    const float* f2b = (const float*)p[13];
    const float* f3w = (const float*)p[14];
    const float* f3b = (const float*)p[15];
    const float* f4w = (const float*)p[16];
    const float* f4b = (const float*)p[17];
    float* out = (float*)d_out;

    cudaFuncSetAttribute(prep_y_kernel, cudaFuncAttributeMaxDynamicSharedMemorySize, SMEM_Y);
    cudaFuncSetAttribute(edge_mlp_kernel, cudaFuncAttributeMaxDynamicSharedMemorySize, SMEM_E);

    detect_idx<<<1, 1>>>((const int*)ei);
    prep_nodes<<<5000, 256>>>(z, cell, esm, mw1, mb1, mw2, mb2, mw3, mb3);
    const int WT = N1 * KW1 + N2 * N1 + N3 * N2;
    prep_weights<<<(WT + 255) / 256, 256>>>(f1w, f2w, f3w);
    prep_y_kernel<<<313, 512, SMEM_Y>>>();
    edge_mlp_kernel<<<(N_EDGES_C + 63) / 64, 256, SMEM_E>>>(
        ei, f1b, f2b, f3b, f4w, f4b, out);
}

// round 14
// speedup vs baseline: 1.2957x; 1.2957x over previous
#include <cuda_runtime.h>
#include <cuda_fp16.h>
#include <cstdint>

#define N_EDGES_C 500000
#define N1 448
#define N2 256
#define N3 128
#define KY 416
#define SA_Y 424
#define SA2 456
#define SA3 264
#define SO3 136
#define SBS32 40
#define SBS64 72
#define BS32BYTES 35840   // prep_y B chunk: 448 x 40 h x 2B
#define BS64BYTES 36864   // edge B chunk max: 256 x 72 h x 2B (w3 chunk 18432)
#define W3CHUNK   18432

__device__ __half g_zc[(size_t)20000 * KY];
// chunk-contiguous pre-strided weights (SMEM image per chunk)
__device__ __half g_w1c[(size_t)26 * 17920];   // [half*13+c][448*40]
__device__ __half g_w2c[(size_t)7 * 18432];    // [c][256*72]
__device__ __half g_w3c[(size_t)4 * 9216];     // [c][128*72]
__device__ __half g_ytop[(size_t)20000 * N1];
__device__ __half g_ybot[(size_t)20000 * N1];
__device__ int g_idx64;

__device__ __forceinline__ uint32_t smem_u32(const void* p) {
    uint32_t a;
    asm("{ .reg .u64 t; cvta.to.shared.u64 t, %1; cvt.u32.u64 %0, t; }" : "=r"(a) : "l"(p));
    return a;
}
#define LDSM4(r0, r1, r2, r3, a) \
    asm volatile("ldmatrix.sync.aligned.m8n8.x4.shared.b16 {%0,%1,%2,%3}, [%4];" \
                 : "=r"(r0), "=r"(r1), "=r"(r2), "=r"(r3) : "r"(a))
#define LDSM2(r0, r1, a) \
    asm volatile("ldmatrix.sync.aligned.m8n8.x2.shared.b16 {%0,%1}, [%2];" \
                 : "=r"(r0), "=r"(r1) : "r"(a))
#define HMMA(d, a0, a1, a2, a3, b0, b1) \
    asm volatile("mma.sync.aligned.m16n8k16.row.col.f32.f16.f16.f32 " \
                 "{%0,%1,%2,%3}, {%4,%5,%6,%7}, {%8,%9}, {%0,%1,%2,%3};" \
                 : "+f"((d)[0]), "+f"((d)[1]), "+f"((d)[2]), "+f"((d)[3]) \
                 : "r"(a0), "r"(a1), "r"(a2), "r"(a3), "r"(b0), "r"(b1))
#define CPA16(dst, src) \
    asm volatile("cp.async.ca.shared.global [%0], [%1], 16;" :: "r"(dst), "l"(src))
#define CPA_COMMIT() asm volatile("cp.async.commit_group;" ::: "memory")
#define CPA_WAIT(n)  asm volatile("cp.async.wait_group %0;" :: "n"(n) : "memory")
#define MB_INIT(a, c) asm volatile("mbarrier.init.shared.b64 [%0], %1;" :: "r"((uint32_t)(a)), "r"((uint32_t)(c)) : "memory")
#define MB_WAIT(a, par) do { \
    uint32_t _m = (uint32_t)(a), _p = (uint32_t)(par), _d; \
    asm volatile("{\n\t.reg .pred p;\n\tmbarrier.try_wait.parity.acquire.cta.shared::cta.b64 p, [%1], %2;\n\tselp.b32 %0, 1, 0, p;\n\t}" \
                 : "=r"(_d) : "r"(_m), "r"(_p) : "memory"); \
    if (!_d) asm volatile("{\n\t.reg .pred P1;\n\tWL_%=:\n\tmbarrier.try_wait.parity.acquire.cta.shared::cta.b64 P1, [%0], %1, 0x989680;\n\t@P1 bra.uni WD_%=;\n\tbra.uni WL_%=;\n\tWD_%=:\n\t}" \
                 :: "r"(_m), "r"(_p) : "memory"); \
} while (0)

// one bulk copy of a pre-strided chunk into buffer (icnt&1); tid0 issues
__device__ __forceinline__ void bulk_issue(uint32_t aB, uint32_t bufbytes,
                                           const __half* src, uint32_t bytes,
                                           uint32_t mb0, uint32_t mb1, int& icnt, int tid) {
    int buf = icnt & 1;
    if (tid == 0) {
        uint32_t mb = buf ? mb1 : mb0;
        uint32_t dst = aB + buf * bufbytes;
        asm volatile("mbarrier.arrive.expect_tx.shared.b64 _, [%0], %1;"
                     :: "r"(mb), "r"(bytes) : "memory");
        asm volatile("cp.async.bulk.shared::cluster.global.mbarrier::complete_tx::bytes [%0], [%1], %2, [%3];"
                     :: "r"(dst), "l"(src), "r"(bytes), "r"(mb) : "memory");
    }
    icnt++;
}
__device__ __forceinline__ int bulk_wait(uint32_t mb0, uint32_t mb1, int& wcnt, int* ph) {
    int buf = wcnt & 1;
    MB_WAIT(buf ? mb1 : mb0, ph[buf]);
    ph[buf] ^= 1;
    wcnt++;
    return buf;
}

__global__ void detect_idx(const int* ei) {
    int z = 0;
    for (int i = 0; i < 64; i++) z |= ei[2 * i + 1];
    g_idx64 = (z == 0) ? 1 : 0;
}

// ---------- P1: node MLP + zc (4 nodes/block) ----------
__global__ void __launch_bounds__(256) prep_nodes(
    const float* __restrict__ z, const float* __restrict__ cell,
    const float* __restrict__ esm,
    const float* __restrict__ w1, const float* __restrict__ b1,
    const float* __restrict__ w2, const float* __restrict__ b2,
    const float* __restrict__ w3, const float* __restrict__ b3) {
    __shared__ float sc[4][4], h1[4][64], h2[4][32], m16[4][16];
    const int sub = threadIdx.x >> 6, t = threadIdx.x & 63;
    const int i = blockIdx.x * 4 + sub;
    if (t < 4) sc[sub][t] = cell[i * 4 + t];
    __syncthreads();
    {
        float s = b1[t];
        for (int j = 0; j < 4; j++) s += sc[sub][j] * w1[j * 64 + t];
        h1[sub][t] = fmaxf(s, 0.f);
    }
    __syncthreads();
    if (t < 32) {
        float s = b2[t];
        for (int j = 0; j < 64; j++) s += h1[sub][j] * w2[j * 32 + t];
        h2[sub][t] = fmaxf(s, 0.f);
    }
    __syncthreads();
    if (t < 16) {
        float s = b3[t];
        for (int j = 0; j < 32; j++) s += h2[sub][j] * w3[j * 16 + t];
        m16[sub][t] = s;
    }
    __syncthreads();
    for (int col = t; col < KY; col += 64) {
        float v = 0.f;
        if (col < 64)       v = z[i * 64 + col];
        else if (col < 80)  v = m16[sub][col - 64];
        else if (col < 400) v = esm[i * 320 + (col - 80)];
        g_zc[(size_t)i * KY + col] = __float2half_rn(v);
    }
}

// ---------- P2: weights -> chunk-contiguous pre-strided f16 ----------
__global__ void prep_weights(const float* __restrict__ fw1, const float* __restrict__ fw2,
                             const float* __restrict__ fw3) {
    int i = blockIdx.x * blockDim.x + threadIdx.x;
    const int T1 = 26 * 17920, T2 = 7 * 18432, T3 = 4 * 9216;
    if (i < T1) {
        int chunk = i / 17920, r = i % 17920;
        int h = chunk / 13, c = chunk % 13;
        int n = r / 40, kk = r % 40;
        int k = c * 32 + kk;
        float v = 0.f;
        if (kk < 32 && n < 400 && k < 400) v = fw1[(h * 400 + k) * 400 + n];
        g_w1c[i] = __float2half_rn(v);
    } else if (i < T1 + T2) {
        int j = i - T1;
        int c = j / 18432, r = j % 18432;
        int n = r / 72, kk = r % 72;
        int k = c * 64 + kk;
        float v = 0.f;
        if (kk < 64 && n < 200 && k < 400) v = fw2[k * 200 + n];
        g_w2c[j] = __float2half_rn(v);
    } else if (i < T1 + T2 + T3) {
        int j = i - T1 - T2;
        int c = j / 9216, r = j % 9216;
        int n = r / 72, kk = r % 72;
        int k = c * 64 + kk;
        float v = 0.f;
        if (kk < 64 && n < 100 && k < 200) v = fw3[k * 100 + n];
        g_w3c[j] = __float2half_rn(v);
    }
}

// ---------- gemm32b: 512 thr, 2Mx8N, k32 chunks, bulk-copied B ----------
template <int NTILES, int NCH>
__device__ __forceinline__ void gemm32b(const __half* __restrict__ Wc,
                                        const __half* __restrict__ Wnextc, uint32_t nextbytes,
                                        uint32_t aA, uint32_t aB, int SA, float* acc,
                                        uint32_t mb0, uint32_t mb1, int& icnt, int& wcnt, int* ph,
                                        int wm, int wn, int lane, int tid) {
#pragma unroll
    for (int i = 0; i < 2 * NTILES * 4; i++) acc[i] = 0.f;
    const uint32_t brow = wn * (NTILES * 8) + (lane & 7) + ((lane >> 4) << 3);
#pragma unroll 1
    for (int c = 0; c < NCH; c++) {
        if (c + 1 < NCH)
            bulk_issue(aB, BS32BYTES, Wc + (size_t)(c + 1) * 17920, BS32BYTES, mb0, mb1, icnt, tid);
        else if (Wnextc)
            bulk_issue(aB, BS32BYTES, Wnextc, nextbytes, mb0, mb1, icnt, tid);
        const int buf = bulk_wait(mb0, mb1, wcnt, ph);
        const uint32_t bbase = aB + buf * BS32BYTES;
#pragma unroll
        for (int s = 0; s < 2; s++) {
            uint32_t aaddr = aA + (((wm * 32 + (lane & 15)) * SA + c * 32 + s * 16 + ((lane >> 4) << 3)) << 1);
            uint32_t a0, a1, a2, a3, e0, e1, e2, e3;
            LDSM4(a0, a1, a2, a3, aaddr);
            LDSM4(e0, e1, e2, e3, aaddr + 16 * SA * 2);
            uint32_t baddr = bbase + ((brow * SBS32 + s * 16 + (((lane >> 3) & 1) << 3)) << 1);
#pragma unroll
            for (int g = 0; g < NTILES / 2; g++) {
                uint32_t b0, b1, b2, b3;
                LDSM4(b0, b1, b2, b3, baddr + g * (16 * SBS32 * 2));
                HMMA(acc + (2 * g) * 4, a0, a1, a2, a3, b0, b1);
                HMMA(acc + (2 * g + 1) * 4, a0, a1, a2, a3, b2, b3);
                HMMA(acc + (NTILES + 2 * g) * 4, e0, e1, e2, e3, b0, b1);
                HMMA(acc + (NTILES + 2 * g + 1) * 4, e0, e1, e2, e3, b2, b3);
            }
            if (NTILES & 1) {
                uint32_t b0, b1;
                LDSM2(b0, b1, baddr + (NTILES / 2) * (16 * SBS32 * 2));
                HMMA(acc + (NTILES - 1) * 4, a0, a1, a2, a3, b0, b1);
                HMMA(acc + (2 * NTILES - 1) * 4, e0, e1, e2, e3, b0, b1);
            }
        }
        __syncthreads();
    }
}

// ---------- prep_y (f16 output, bulk W) ----------
#define SMY_MB 0
#define SMY_A  64
#define SMY_B  (64 + 54272)
#define SMEM_Y (SMY_B + 2 * BS32BYTES)   // 126016

__global__ void __launch_bounds__(512) prep_y_kernel() {
    extern __shared__ char smem[];
    const uint32_t mb0 = smem_u32(smem + SMY_MB);
    const uint32_t mb1 = mb0 + 8;
    const uint32_t aA = smem_u32(smem + SMY_A);
    const uint32_t aB = smem_u32(smem + SMY_B);
    const int tid = threadIdx.x;
    const int wid = tid >> 5, lane = tid & 31;
    const int wm = wid & 1, wn = wid >> 1;
    const int base = blockIdx.x * 64;

    if (tid == 0) { MB_INIT(mb0, 1); MB_INIT(mb1, 1); }
    __syncthreads();

    int icnt = 0, wcnt = 0, ph[2] = {0, 0};
    bulk_issue(aB, BS32BYTES, g_w1c, BS32BYTES, mb0, mb1, icnt, tid);  // half0 chunk0

    for (int i = tid; i < 64 * 52; i += 512) {
        int r = i / 52, u = i % 52;
        int grow = base + r; if (grow > 19999) grow = 19999;
        CPA16(aA + ((r * SA_Y + u * 8) << 1), g_zc + (size_t)grow * KY + u * 8);
    }
    CPA_COMMIT(); CPA_WAIT(0);
    __syncthreads();

    float acc[56];
    gemm32b<7, 13>(g_w1c, g_w1c + (size_t)13 * 17920, BS32BYTES,
                   aA, aB, SA_Y, acc, mb0, mb1, icnt, wcnt, ph, wm, wn, lane, tid);
#pragma unroll
    for (int mt = 0; mt < 2; mt++) {
        int r0 = base + wm * 32 + mt * 16 + (lane >> 2);
#pragma unroll
        for (int nt = 0; nt < 7; nt++) {
            int c = wn * 56 + nt * 8 + (lane & 3) * 2;
            float* d = acc + (mt * 7 + nt) * 4;
            if (r0 < 20000) *(__half2*)(g_ytop + (size_t)r0 * N1 + c) = __floats2half2_rn(d[0], d[1]);
            if (r0 + 8 < 20000) *(__half2*)(g_ytop + (size_t)(r0 + 8) * N1 + c) = __floats2half2_rn(d[2], d[3]);
        }
    }
    gemm32b<7, 13>(g_w1c + (size_t)13 * 17920, nullptr, 0,
                   aA, aB, SA_Y, acc, mb0, mb1, icnt, wcnt, ph, wm, wn, lane, tid);
#pragma unroll
    for (int mt = 0; mt < 2; mt++) {
        int r0 = base + wm * 32 + mt * 16 + (lane >> 2);
#pragma unroll
        for (int nt = 0; nt < 7; nt++) {
            int c = wn * 56 + nt * 8 + (lane & 3) * 2;
            float* d = acc + (mt * 7 + nt) * 4;
            if (r0 < 20000) *(__half2*)(g_ybot + (size_t)r0 * N1 + c) = __floats2half2_rn(d[0], d[1]);
            if (r0 + 8 < 20000) *(__half2*)(g_ybot + (size_t)(r0 + 8) * N1 + c) = __floats2half2_rn(d[2], d[3]);
        }
    }
}

// ---------- gemm64b: 512 thr, 4Mx4N, k64 chunks, bulk B ----------
template <int NTILES, int NCH>
__device__ __forceinline__ void gemm64b(const __half* __restrict__ Wc, uint32_t chunkbytes,
                                        const __half* __restrict__ Wnextc, uint32_t nextbytes,
                                        uint32_t aA, uint32_t aB, int SA, float* acc,
                                        uint32_t mb0, uint32_t mb1, int& icnt, int& wcnt, int* ph,
                                        int wm, int wn, int lane, int tid) {
#pragma unroll
    for (int i = 0; i < 2 * NTILES * 4; i++) acc[i] = 0.f;
    const uint32_t brow = wn * (NTILES * 8) + (lane & 7) + ((lane >> 4) << 3);
#pragma unroll 1
    for (int c = 0; c < NCH; c++) {
        if (c + 1 < NCH)
            bulk_issue(aB, BS64BYTES, Wc + (size_t)(c + 1) * (chunkbytes / 2), chunkbytes, mb0, mb1, icnt, tid);
        else if (Wnextc)
            bulk_issue(aB, BS64BYTES, Wnextc, nextbytes, mb0, mb1, icnt, tid);
        const int buf = bulk_wait(mb0, mb1, wcnt, ph);
        const uint32_t bbase = aB + buf * BS64BYTES;
#pragma unroll
        for (int s = 0; s < 4; s++) {
            uint32_t aaddr = aA + (((wm * 32 + (lane & 15)) * SA + c * 64 + s * 16 + ((lane >> 4) << 3)) << 1);
            uint32_t a0, a1, a2, a3, e0, e1, e2, e3;
            LDSM4(a0, a1, a2, a3, aaddr);
            LDSM4(e0, e1, e2, e3, aaddr + 16 * SA * 2);
            uint32_t baddr = bbase + ((brow * SBS64 + s * 16 + (((lane >> 3) & 1) << 3)) << 1);
#pragma unroll
            for (int g = 0; g < NTILES / 2; g++) {
                uint32_t b0, b1, b2, b3;
                LDSM4(b0, b1, b2, b3, baddr + g * (16 * SBS64 * 2));
                HMMA(acc + (2 * g) * 4, a0, a1, a2, a3, b0, b1);
                HMMA(acc + (2 * g + 1) * 4, a0, a1, a2, a3, b2, b3);
                HMMA(acc + (NTILES + 2 * g) * 4, e0, e1, e2, e3, b0, b1);
                HMMA(acc + (NTILES + 2 * g + 1) * 4, e0, e1, e2, e3, b2, b3);
            }
        }
        __syncthreads();
    }
}

template <int NTILES>
__device__ __forceinline__ void epi(float* acc, __half* A, int SO, const float* bias,
                                    int wm, int wn, int lane) {
#pragma unroll
    for (int mt = 0; mt < 2; mt++) {
        int r0 = wm * 32 + mt * 16 + (lane >> 2);
#pragma unroll
        for (int nt = 0; nt < NTILES; nt++) {
            int c = wn * (NTILES * 8) + nt * 8 + (lane & 3) * 2;
            float* d = acc + (mt * NTILES + nt) * 4;
            *(__half2*)(A + r0 * SO + c) =
                __floats2half2_rn(fmaxf(d[0] + bias[c], 0.f), fmaxf(d[1] + bias[c + 1], 0.f));
            *(__half2*)(A + (r0 + 8) * SO + c) =
                __floats2half2_rn(fmaxf(d[2] + bias[c], 0.f), fmaxf(d[3] + bias[c + 1], 0.f));
        }
    }
}

// ---------- edge kernel: M=128, 512 thr ----------
#define SME_MB   0
#define SME_NS   64
#define SME_ND   576
#define SME_BIAS 1088
#define SME_A    5056                      // 128 x 456 h = 116736
#define SME_B    121792                    // 2 x 36864
#define SMEM_E   (SME_B + 2 * BS64BYTES)   // 195520

__global__ void __launch_bounds__(512) edge_mlp_kernel(
    const void* __restrict__ eidx_raw, const float* __restrict__ fb1,
    const float* __restrict__ fb2, const float* __restrict__ fb3,
    const float* __restrict__ fw4, const float* __restrict__ fb4,
    float* __restrict__ out) {
    extern __shared__ char smem[];
    const uint32_t mb0 = smem_u32(smem + SME_MB);
    const uint32_t mb1 = mb0 + 8;
    int* ns = (int*)(smem + SME_NS);
    int* nd = (int*)(smem + SME_ND);
    float* bias = (float*)(smem + SME_BIAS);
    __half* A = (__half*)(smem + SME_A);
    const uint32_t aA = smem_u32(A);
    const uint32_t aB = smem_u32(smem + SME_B);

    const int tid = threadIdx.x;
    const int wid = tid >> 5, lane = tid & 31;
    const int wm = wid & 3, wn = wid >> 2;
    const long long base = (long long)blockIdx.x * 128;

    if (tid == 0) { MB_INIT(mb0, 1); MB_INIT(mb1, 1); }
    __syncthreads();

    int icnt = 0, wcnt = 0, ph[2] = {0, 0};
    bulk_issue(aB, BS64BYTES, g_w2c, BS64BYTES, mb0, mb1, icnt, tid);  // W2 chunk0, overlaps combine

    for (int i = tid; i < 448; i += 512) bias[i] = (i < 400) ? fb1[i] : 0.f;
    if (tid < 256) bias[448 + tid] = (tid < 200) ? fb2[tid] : 0.f;
    else if (tid < 384) { int i = tid - 256; bias[704 + i] = (i < 100) ? fb3[i] : 0.f; }
    else { int i = tid - 384; bias[832 + i] = (i < 100) ? fw4[i] : 0.f; }
    if (tid == 0) bias[960] = fb4[0];

    if (tid < 128) {
        long long e = base + tid;
        if (e >= N_EDGES_C) e = N_EDGES_C - 1;
        if (g_idx64) {
            const long long* ei = (const long long*)eidx_raw;
            ns[tid] = (int)ei[e]; nd[tid] = (int)ei[N_EDGES_C + e];
        } else {
            const int* ei = (const int*)eidx_raw;
            ns[tid] = ei[e]; nd[tid] = ei[N_EDGES_C + e];
        }
    }
    __syncthreads();

    // combine: act1[128][448] = f16(relu(f32(yt) + f32(yb) + b1))
    for (int i = tid; i < 128 * 56; i += 512) {
        int r = i / 56, u = i % 56;
        uint4 tv = *(const uint4*)(g_ytop + (size_t)ns[r] * N1 + u * 8);
        uint4 bv = *(const uint4*)(g_ybot + (size_t)nd[r] * N1 + u * 8);
        const __half2* tp = (const __half2*)&tv;
        const __half2* bp = (const __half2*)&bv;
        const float* bb = bias + u * 8;
        __half2 h[4];
#pragma unroll
        for (int j = 0; j < 4; j++) {
            float2 t2 = __half22float2(tp[j]);
            float2 b2 = __half22float2(bp[j]);
            h[j] = __floats2half2_rn(fmaxf(t2.x + b2.x + bb[2 * j], 0.f),
                                     fmaxf(t2.y + b2.y + bb[2 * j + 1], 0.f));
        }
        *(uint4*)(A + r * SA2 + u * 8) = *(uint4*)h;
    }
    __syncthreads();

    float acc[64];
    // FC2: [128,448] @ W2 -> 256 (7 k64 chunks; last chunk prefetches W3 chunk0)
    gemm64b<8, 7>(g_w2c, BS64BYTES, g_w3c, W3CHUNK,
                  aA, aB, SA2, acc, mb0, mb1, icnt, wcnt, ph, wm, wn, lane, tid);
    epi<8>(acc, A, SA3, bias + 448, wm, wn, lane);
    __syncthreads();
    // FC3: [128,256] @ W3 -> 128 (4 k64 chunks)
    gemm64b<4, 4>(g_w3c, W3CHUNK, nullptr, 0,
                  aA, aB, SA3, acc, mb0, mb1, icnt, wcnt, ph, wm, wn, lane, tid);
    epi<4>(acc, A, SO3, bias + 704, wm, wn, lane);
    __syncthreads();

    // head: warp-cooperative dot, 8 edges/warp
#pragma unroll 1
    for (int q = 0; q < 8; q++) {
        int r = wid * 8 + q;
        const __half* ar = A + r * SO3;
        float s = 0.f;
#pragma unroll
        for (int j = 0; j < 4; j++) {
            int c = lane + j * 32;
            if (c < 100) s += __half2float(ar[c]) * bias[832 + c];
        }
#pragma unroll
        for (int o = 16; o; o >>= 1) s += __shfl_xor_sync(~0u, s, o);
        if (lane == 0) {
            long long e = base + r;
            if (e < N_EDGES_C) out[e] = s + bias[960];
        }
    }
}

extern "C" void kernel_launch(void* const* d_in, const int* in_sizes, int n_in,
                              void* d_out, int out_size) {
    static const int EXP[18] = {1280000, 1000000, 80000, 6400000, 256, 64, 2048, 32, 512, 16,
                                320000, 400, 80000, 200, 20000, 100, 100, 1};
    const void* p[18];
    bool used[32] = {false};
    for (int j = 0; j < 18; j++) {
        p[j] = (j < n_in) ? d_in[j] : nullptr;
        for (int i = 0; i < n_in && i < 32; i++) {
            if (!used[i] && in_sizes[i] == EXP[j]) { p[j] = d_in[i]; used[i] = true; break; }
        }
    }
    const float* z    = (const float*)p[0];
    const void*  ei   = p[1];
    const float* cell = (const float*)p[2];
    const float* esm  = (const float*)p[3];
    const float* mw1 = (const float*)p[4];
    const float* mb1 = (const float*)p[5];
    const float* mw2 = (const float*)p[6];
    const float* mb2 = (const float*)p[7];
    const float* mw3 = (const float*)p[8];
    const float* mb3 = (const float*)p[9];
    const float* f1w = (const float*)p[10];
    const float* f1b = (const float*)p[11];
    const float* f2w = (const float*)p[12];
    const float* f2b = (const float*)p[13];
    const float* f3w = (const float*)p[14];
    const float* f3b = (const float*)p[15];
    const float* f4w = (const float*)p[16];
    const float* f4b = (const float*)p[17];
    float* out = (float*)d_out;

    cudaFuncSetAttribute(prep_y_kernel, cudaFuncAttributeMaxDynamicSharedMemorySize, SMEM_Y);
    cudaFuncSetAttribute(edge_mlp_kernel, cudaFuncAttributeMaxDynamicSharedMemorySize, SMEM_E);

    detect_idx<<<1, 1>>>((const int*)ei);
    prep_nodes<<<5000, 256>>>(z, cell, esm, mw1, mb1, mw2, mb2, mw3, mb3);
    const int WT = 26 * 17920 + 7 * 18432 + 4 * 9216;
    prep_weights<<<(WT + 255) / 256, 256>>>(f1w, f2w, f3w);
    prep_y_kernel<<<313, 512, SMEM_Y>>>();
    edge_mlp_kernel<<<(N_EDGES_C + 127) / 128, 512, SMEM_E>>>(
        ei, f1b, f2b, f3b, f4w, f4b, out);
}